// round 1
// baseline (speedup 1.0000x reference)
#include <cuda_runtime.h>

#define NB      16384
#define NA      64
#define DIN     128
#define NH1     32
#define NH2     16
#define NITERS  200
#define POW_ITERS 300

typedef unsigned long long u64;

__device__ float g_step;
__device__ float g_p[NB * NA];

__device__ __forceinline__ u64 pack2(float x, float y) {
    u64 r; asm("mov.b64 %0, {%1,%2};" : "=l"(r) : "f"(x), "f"(y)); return r;
}
__device__ __forceinline__ void unpack2(u64 v, float& x, float& y) {
    asm("mov.b64 {%0,%1}, %2;" : "=f"(x), "=f"(y) : "l"(v));
}
__device__ __forceinline__ u64 ffma2(u64 a, u64 b, u64 c) {
    u64 d; asm("fma.rn.f32x2 %0, %1, %2, %3;" : "=l"(d) : "l"(a), "l"(b), "l"(c)); return d;
}

// ---------------------------------------------------------------------------
// Kernel 1: largest eigenvalue of sigma (64x64 SPD) via power iteration,
// Rayleigh quotient estimate. Writes g_step = 1/lambda_max.
// ---------------------------------------------------------------------------
__global__ void power_kernel(const float* __restrict__ sigma) {
    __shared__ float sig[NA * (NA + 1)];        // padded rows -> conflict-free
    __shared__ __align__(16) float v[NA];
    __shared__ float red[4];
    int tid = threadIdx.x;                      // 64 threads

    for (int i = tid; i < NA * NA; i += 64)
        sig[(i >> 6) * (NA + 1) + (i & 63)] = sigma[i];
    v[tid] = 1.0f;
    __syncthreads();

    float lambda = 1.0f;
    for (int it = 0; it < POW_ITERS; ++it) {
        const float* row = &sig[tid * (NA + 1)];
        float a0 = 0.f, a1 = 0.f, a2 = 0.f, a3 = 0.f;
        #pragma unroll
        for (int k = 0; k < NA; k += 4) {
            float4 vv = *reinterpret_cast<const float4*>(&v[k]);
            a0 = fmaf(row[k + 0], vv.x, a0);
            a1 = fmaf(row[k + 1], vv.y, a1);
            a2 = fmaf(row[k + 2], vv.z, a2);
            a3 = fmaf(row[k + 3], vv.w, a3);
        }
        float zi = (a0 + a1) + (a2 + a3);
        float dt = v[tid] * zi;     // Rayleigh numerator (v unit-norm for it>=1)
        float nr = zi * zi;
        #pragma unroll
        for (int o = 16; o > 0; o >>= 1) {
            dt += __shfl_xor_sync(0xffffffffu, dt, o);
            nr += __shfl_xor_sync(0xffffffffu, nr, o);
        }
        __syncthreads();
        if ((tid & 31) == 0) { red[tid >> 5] = dt; red[2 + (tid >> 5)] = nr; }
        __syncthreads();
        lambda = red[0] + red[1];
        float rinv = rsqrtf(red[2] + red[3]);
        v[tid] = zi * rinv;
        __syncthreads();
    }
    if (tid == 0) g_step = 1.0f / lambda;
}

// ---------------------------------------------------------------------------
// Kernel 2: MLP -> mu (written to output) and p = -gamma*mu (scratch).
// One warp per row; weights staged in shared memory.
// ---------------------------------------------------------------------------
__global__ __launch_bounds__(256) void mlp_kernel(
    const float* __restrict__ x,  const float* __restrict__ W1, const float* __restrict__ b1,
    const float* __restrict__ W2, const float* __restrict__ b2,
    const float* __restrict__ W3, const float* __restrict__ b3,
    const float* __restrict__ gamma, float* __restrict__ out_mu)
{
    __shared__ float W1s[DIN * NH1];
    __shared__ float W2s[NH1 * NH2];
    __shared__ float W3s[NH2 * NA];
    __shared__ float b1s[NH1], b2s[NH2], b3s[NA];
    __shared__ __align__(16) float xs[8][DIN];
    __shared__ float h1s[8][NH1];
    __shared__ float h2s[8][NH2];

    int tid = threadIdx.x;
    for (int i = tid; i < DIN * NH1; i += 256) W1s[i] = W1[i];
    for (int i = tid; i < NH1 * NH2; i += 256) W2s[i] = W2[i];
    for (int i = tid; i < NH2 * NA;  i += 256) W3s[i] = W3[i];
    if (tid < NH1) b1s[tid] = b1[tid];
    if (tid < NH2) b2s[tid] = b2[tid];
    if (tid < NA)  b3s[tid] = b3[tid];
    __syncthreads();

    int warp = tid >> 5, lane = tid & 31;
    int row = blockIdx.x * 8 + warp;
    float g = gamma[0];

    #pragma unroll
    for (int q = 0; q < 4; ++q)
        xs[warp][lane + 32 * q] = x[row * DIN + lane + 32 * q];
    __syncwarp();

    // h1 = relu(x @ W1 + b1): lane computes output channel `lane`
    float acc = b1s[lane];
    #pragma unroll
    for (int d = 0; d < DIN; d += 4) {
        float4 xv = *reinterpret_cast<const float4*>(&xs[warp][d]);
        acc = fmaf(xv.x, W1s[(d + 0) * NH1 + lane], acc);
        acc = fmaf(xv.y, W1s[(d + 1) * NH1 + lane], acc);
        acc = fmaf(xv.z, W1s[(d + 2) * NH1 + lane], acc);
        acc = fmaf(xv.w, W1s[(d + 3) * NH1 + lane], acc);
    }
    h1s[warp][lane] = fmaxf(acc, 0.0f);
    __syncwarp();

    // h2 = relu(h1 @ W2 + b2): lanes 0..15
    if (lane < NH2) {
        float a2 = b2s[lane];
        #pragma unroll
        for (int d = 0; d < NH1; ++d)
            a2 = fmaf(h1s[warp][d], W2s[d * NH2 + lane], a2);
        h2s[warp][lane] = fmaxf(a2, 0.0f);
    }
    __syncwarp();

    // mu = h2 @ W3 + b3: lane computes cols lane and lane+32
    float m0 = b3s[lane], m1 = b3s[lane + 32];
    #pragma unroll
    for (int d = 0; d < NH2; ++d) {
        float h = h2s[warp][d];
        m0 = fmaf(h, W3s[d * NA + lane], m0);
        m1 = fmaf(h, W3s[d * NA + lane + 32], m1);
    }
    out_mu[row * NA + lane]      = m0;
    out_mu[row * NA + lane + 32] = m1;
    g_p[row * NA + lane]      = -g * m0;
    g_p[row * NA + lane + 32] = -g * m1;
}

// ---------------------------------------------------------------------------
// Kernel 3: FISTA with exact simplex projection (Michelot active-set).
// One warp processes RPW rows; lane owns components (lane, lane+32).
// Matvec uses f32x2 packed FMA: sp[k][j] = (sigma[k][j], sigma[k][j+32]),
// y broadcast from smem pre-duplicated as (y_k, y_k).
// ---------------------------------------------------------------------------
#define FW   4      // warps per block
#define RPW  4      // rows per warp
#define RPB  (FW * RPW)

__global__ __launch_bounds__(128) void fista_kernel(
    const float* __restrict__ sigma, float* __restrict__ out_w)
{
    __shared__ __align__(16) u64 sp[NA][32];          // 16 KB packed sigma
    __shared__ __align__(16) u64 ydup[FW][RPW][NA];   // 8 KB duplicated y

    int tid = threadIdx.x;
    int warp = tid >> 5, lane = tid & 31;

    for (int i = tid; i < NA * 32; i += 128) {
        int k = i >> 5, j = i & 31;
        sp[k][j] = pack2(sigma[k * NA + j], sigma[k * NA + j + 32]);
    }
    __syncthreads();

    float step = g_step;
    int row0 = blockIdx.x * RPB + warp * RPW;

    float px[RPW], py[RPW], wx[RPW], wy[RPW], yx[RPW], yy[RPW];
    #pragma unroll
    for (int r = 0; r < RPW; ++r) {
        px[r] = g_p[(row0 + r) * NA + lane];
        py[r] = g_p[(row0 + r) * NA + lane + 32];
        wx[r] = wy[r] = yx[r] = yy[r] = 1.0f / 64.0f;
    }
    float t = 1.0f;

    #pragma unroll 1
    for (int it = 0; it < NITERS; ++it) {
        __syncwarp();
        #pragma unroll
        for (int r = 0; r < RPW; ++r) {
            ydup[warp][r][lane]      = pack2(yx[r], yx[r]);
            ydup[warp][r][lane + 32] = pack2(yy[r], yy[r]);
        }
        __syncwarp();

        // grad = y @ sigma + p  (f32x2 packed)
        u64 g[RPW];
        #pragma unroll
        for (int r = 0; r < RPW; ++r) g[r] = pack2(px[r], py[r]);

        #pragma unroll
        for (int k = 0; k < NA; k += 2) {
            u64 s0 = sp[k][lane];
            u64 s1 = sp[k + 1][lane];
            #pragma unroll
            for (int r = 0; r < RPW; ++r) {
                ulonglong2 yk = *reinterpret_cast<const ulonglong2*>(&ydup[warp][r][k]);
                g[r] = ffma2(yk.x, s0, g[r]);
                g[r] = ffma2(yk.y, s1, g[r]);
            }
        }

        // FISTA momentum scalars (warp-uniform, matches reference fp32 math)
        float tn = 0.5f * (1.0f + sqrtf(1.0f + 4.0f * t * t));
        float beta = (t - 1.0f) / tn;
        t = tn;

        #pragma unroll
        for (int r = 0; r < RPW; ++r) {
            float gx, gy;
            unpack2(g[r], gx, gy);
            float vx = fmaf(-step, gx, yx[r]);
            float vy = fmaf(-step, gy, yy[r]);

            // Michelot: exact Euclidean projection onto the simplex.
            bool ax = true, ay = true;
            float theta = 0.0f;
            #pragma unroll 1
            for (int pass = 0; pass < NA; ++pass) {
                float S = (ax ? vx : 0.0f) + (ay ? vy : 0.0f);
                float C = (ax ? 1.0f : 0.0f) + (ay ? 1.0f : 0.0f);
                #pragma unroll
                for (int o = 16; o > 0; o >>= 1) {
                    S += __shfl_xor_sync(0xffffffffu, S, o);
                    C += __shfl_xor_sync(0xffffffffu, C, o);
                }
                theta = (S - 1.0f) / C;
                bool rx = ax && (vx <= theta);
                bool ry = ay && (vy <= theta);
                if (!__any_sync(0xffffffffu, rx || ry)) break;
                ax = ax && !rx;
                ay = ay && !ry;
            }
            float wnx = ax ? (vx - theta) : 0.0f;
            float wny = ay ? (vy - theta) : 0.0f;

            yx[r] = fmaf(beta, wnx - wx[r], wnx);
            yy[r] = fmaf(beta, wny - wy[r], wny);
            wx[r] = wnx;
            wy[r] = wny;
        }
    }

    #pragma unroll
    for (int r = 0; r < RPW; ++r) {
        out_w[(row0 + r) * NA + lane]      = wx[r];
        out_w[(row0 + r) * NA + lane + 32] = wy[r];
    }
}

// ---------------------------------------------------------------------------
extern "C" void kernel_launch(void* const* d_in, const int* in_sizes, int n_in,
                              void* d_out, int out_size) {
    const float* x     = (const float*)d_in[0];
    const float* W1    = (const float*)d_in[1];
    const float* b1    = (const float*)d_in[2];
    const float* W2    = (const float*)d_in[3];
    const float* b2    = (const float*)d_in[4];
    const float* W3    = (const float*)d_in[5];
    const float* b3    = (const float*)d_in[6];
    const float* sigma = (const float*)d_in[7];
    const float* gamma = (const float*)d_in[8];

    float* out    = (float*)d_out;
    float* out_w  = out;                 // weights: [B, 64]
    float* out_mu = out + NB * NA;       // mu:      [B, 64]

    power_kernel<<<1, 64>>>(sigma);
    mlp_kernel<<<NB / 8, 256>>>(x, W1, b1, W2, b2, W3, b3, gamma, out_mu);
    fista_kernel<<<NB / RPB, 128>>>(sigma, out_w);
}